// round 10
// baseline (speedup 1.0000x reference)
#include <cuda_runtime.h>

#define BATCH   2
#define CF      64
#define NXD     468
#define NYD     468
#define GRID    (NXD * NYD)      // 219024
#define NP_PER  60000
#define HRD     48
#define WRD     512
#define RSP     (HRD * WRD)      // 24576
#define TCELL   64               // cells per gather tile (last tile has 16)
#define NTILES  ((GRID + TCELL - 1) / TCELL)   // 3423

// Winner-index maps: [0 .. B*G) spatial, [B*G .. 2*B*G) bev. -1 = empty.
__device__ __align__(16) int g_win[2 * BATCH * GRID];
// Channel-last transposed range_out: [B][RSP][64]
__device__ __align__(16) float g_rot[BATCH * RSP * CF];

#define SCAT_BLOCKS 625          // ceil(160000/256)
#define TRANS_BLOCKS (RSP / 32 * (CF / 32) * BATCH)   // 3072

// Fused prologue: blocks [0,625) scatter winners; blocks [625,3697) transpose
// range_out. Last-write-wins == highest point index (serial XLA scatter order).
// XLA's arcp rewrite makes v/0.16f == v*6.25f exactly (verified rel_err==0.0).
__global__ void __launch_bounds__(256) k_prologue(
        const int* __restrict__ vc, const float* __restrict__ lp,
        const float* __restrict__ ro, int n_pillar, int n_laser) {
    if (blockIdx.x < SCAT_BLOCKS) {
        int i = blockIdx.x * 256 + threadIdx.x;
        if (i < n_pillar) {
            int b   = vc[i * 4 + 0];
            int lin = vc[i * 4 + 1] + vc[i * 4 + 2] * NXD + vc[i * 4 + 3];
            if (b < 0 || b >= BATCH || lin < 0 || lin >= GRID) return;
            atomicMax(&g_win[b * GRID + lin], i);
        } else {
            int p = i - n_pillar;
            if (p >= n_laser) return;
            float x = lp[p * 5 + 1];
            float y = lp[p * 5 + 2];
            bool valid = (x > 0.0f) && (x < 69.12f) && (y > -39.68f) && (y < 39.68f)
                      && (x >= 0.0f) && (x < 468.0f) && (y >= 0.0f) && (y < 468.0f);
            if (!valid) return;
            int xi = (int)__fmul_rn(-y, 6.25f) + 248;   // XOFF
            int yi = (int)__fmul_rn(-x, 6.25f) + 432;   // YOFF
            xi = min(max(xi, 0), 495);
            yi = min(max(yi, 0), 431);
            if (xi >= NXD) return;                      // mode='drop'
            int b = p / NP_PER;
            atomicMax(&g_win[BATCH * GRID + b * GRID + yi * NXD + xi], p);
        }
    } else {
        // Transpose range_out (B,64,RSP) -> g_rot (B,RSP,64), 32x32 tiles.
        __shared__ float tile[32][33];
        int j  = blockIdx.x - SCAT_BLOCKS;
        int s0 = (j % (RSP / 32)) * 32;
        int c0 = ((j / (RSP / 32)) % (CF / 32)) * 32;
        int b  = j / (RSP / 32 * (CF / 32));
        int tx = threadIdx.x & 31, ty = threadIdx.x >> 5;   // (32, 8)
        #pragma unroll
        for (int k = 0; k < 4; k++) {
            int c = c0 + ty + k * 8;
            tile[ty + k * 8][tx] = ro[((size_t)(b * CF + c)) * RSP + s0 + tx];
        }
        __syncthreads();
        #pragma unroll
        for (int k = 0; k < 4; k++) {
            int s = s0 + ty + k * 8;
            g_rot[((size_t)(b * RSP + s)) * CF + c0 + tx] = tile[tx][ty + k * 8];
        }
    }
}

// Half-tile gather: one block = 64 cells x 64 channels (one half of the
// channel dim, picked by blockIdx.z: 0 = spatial/pf, 1 = bev/rot). Small
// blocks (8.3 KB smem, ~28 regs, ONE barrier) -> 8 blocks/SM; cross-block
// interleaving overlaps loads and stores. Loads stay full-row coalesced:
// cell = p*16 + (t>>4), v = t&15 -> 16 lanes read a winner row's 256B =>
// 4 cache lines per warp-LDG. XOR swizzle col = cell ^ 2v gives conflict-
// free scalar STS; store phase reads quad 4*(cv^(cl>>3)) of row cl with a
// branchless half-swap when (cl>>2)&1, then STG.128 (256B/16 lanes).
__global__ void __launch_bounds__(256, 8) k_gather(
        const float* __restrict__ pf,
        const int*   __restrict__ lx,
        const int*   __restrict__ ly,
        const float* __restrict__ lp,
        float*       __restrict__ out) {
    __shared__ float s_val[64][64];        // 16 KB? no: 64*64*4 = 16 KB... half!
    // NOTE: 64 ch x 64 cells x 4B = 16 KB. (8 blocks x 16 KB = 128 KB < 228 KB OK)
    __shared__ float s_zc[TCELL];
    __shared__ int   s_w[TCELL];           // winner (spatial) or rot offset (bev)

    int tile = blockIdx.x;
    int b    = blockIdx.y;
    int half = blockIdx.z;                 // 0 = spatial, 1 = bev
    int t    = threadIdx.x;
    int cell0  = tile * TCELL;
    int ncells = min(TCELL, GRID - cell0);

    if (t < TCELL) {
        if (half == 0) {
            s_w[t] = (t < ncells) ? g_win[b * GRID + cell0 + t] : -1;
        } else {
            int wiB = (t < ncells) ? g_win[BATCH * GRID + b * GRID + cell0 + t] : -1;
            float zc = 0.0f; int off = -1;
            if (wiB >= 0) {
                float z = lp[wiB * 5 + 3];
                zc  = fminf(fmaxf(z, -2.0f), 4.0f);
                off = b * RSP + ly[wiB * 2 + 1] * WRD + lx[wiB * 2 + 1];
            }
            s_zc[t] = zc; s_w[t] = off;
        }
    }
    __syncthreads();

    int crel = t >> 4;                     // 0..15
    int v    = t & 15;                     // quad within 64-ch row

    // Load 4 passes (full-row coalesced) and STS with XOR swizzle.
    #pragma unroll
    for (int p = 0; p < 4; p++) {
        int cell = p * 16 + crel;
        int w = s_w[cell];
        float4 d = make_float4(0.f, 0.f, 0.f, 0.f);
        if (half == 0) {
            if (w >= 0) d = *(const float4*)&pf[(size_t)w * CF + v * 4];
        } else {
            if (w >= 0) {
                float zc = s_zc[cell];
                d = *(const float4*)&g_rot[(size_t)w * CF + v * 4];
                d.x = __fmul_rn(zc, d.x); d.y = __fmul_rn(zc, d.y);
                d.z = __fmul_rn(zc, d.z); d.w = __fmul_rn(zc, d.w);
            }
        }
        int col = (cell ^ (2 * v)) & 63;
        s_val[v * 4 + 0][col] = d.x;
        s_val[v * 4 + 1][col] = d.y;
        s_val[v * 4 + 2][col] = d.z;
        s_val[v * 4 + 3][col] = d.w;
    }
    __syncthreads();

    // Store: 1024 quads (64 ch x 16 cell-quads), 4 per thread.
    size_t base = (size_t)b * 128 * GRID + (size_t)half * CF * GRID + (size_t)cell0;
    #pragma unroll
    for (int it = 0; it < 4; it++) {
        int s  = t + it * 256;
        int cl = s >> 4;                   // channel-local 0..63
        int cv = s & 15;                   // cell quad
        if (cv * 4 < ncells) {
            int G = cv ^ (cl >> 3);
            float4 o = *(const float4*)&s_val[cl][G * 4];
            if ((cl >> 2) & 1) o = make_float4(o.z, o.w, o.x, o.y);
            __stcs((float4*)&out[base + (size_t)cl * GRID + cv * 4], o);
        }
    }
}

extern "C" void kernel_launch(void* const* d_in, const int* in_sizes, int n_in,
                              void* d_out, int out_size) {
    const float* pf = (const float*)d_in[0];   // pillar_features (B*P_PER, 64)
    const int*   vc = (const int*)  d_in[1];   // voxel_coords    (B*P_PER, 4)
    const float* ro = (const float*)d_in[2];   // range_out       (B, 64, 48, 512)
    const int*   lx = (const int*)  d_in[3];   // laser_x         (B*NP, 2)
    const int*   ly = (const int*)  d_in[4];   // laser_y         (B*NP, 2)
    const float* lp = (const float*)d_in[5];   // laser_points    (B*NP, 5)
    float* out = (float*)d_out;

    int n_pillar = in_sizes[1] / 4;
    int n_laser  = in_sizes[5] / 5;

    void* winp = nullptr;
    cudaGetSymbolAddress(&winp, g_win);
    cudaMemsetAsync(winp, 0xFF, sizeof(int) * 2 * BATCH * GRID, 0);  // all -1

    k_prologue<<<SCAT_BLOCKS + TRANS_BLOCKS, 256>>>(vc, lp, ro, n_pillar, n_laser);

    dim3 gg(NTILES, BATCH, 2);                 // (3423, 2, 2)
    k_gather<<<gg, 256>>>(pf, lx, ly, lp, out);
}